// round 16
// baseline (speedup 1.0000x reference)
#include <cuda_runtime.h>
#include <cuda_fp16.h>
#include <cstdint>

#define NN 50000
#define EE 800000
#define HH 8
#define CC 32
#define HSZ 256
#define NEG_SLOPE 0.2f
#define EPSV 1e-16f

// ---------------- device scratch (static, no allocation) ----------------
__device__ __align__(16) __half g_xwh[(size_t)NN * HSZ];  // x @ W in fp16  25.6MB
__device__ float g_asrc[NN * HH];
__device__ float g_adst[NN * HH];
__device__ __align__(16) __half g_wt[HSZ * HSZ];          // W^T fp16 [n][k]
__device__ int   g_deg[NN];
__device__ int   g_off[NN + 1];
__device__ int   g_cur[NN];
__device__ int   g_csr_src[EE];
__device__ int   g_is64;

// ---------------- ptx helpers ----------------
__device__ __forceinline__ uint32_t smem_u32(const void* p) {
    uint32_t a;
    asm("{ .reg .u64 t; cvta.to.shared.u64 t, %1; cvt.u32.u64 %0, t; }" : "=r"(a) : "l"(p));
    return a;
}
__device__ __forceinline__ void ldsm_x4(uint32_t* r, uint32_t addr) {
    asm volatile("ldmatrix.sync.aligned.m8n8.x4.shared.b16 {%0,%1,%2,%3}, [%4];"
                 : "=r"(r[0]), "=r"(r[1]), "=r"(r[2]), "=r"(r[3]) : "r"(addr));
}
__device__ __forceinline__ void mma_f16(float* c, const uint32_t* a, const uint32_t* b) {
    asm volatile("mma.sync.aligned.m16n8k16.row.col.f32.f16.f16.f32 "
                 "{%0,%1,%2,%3}, {%4,%5,%6,%7}, {%8,%9}, {%0,%1,%2,%3};"
                 : "+f"(c[0]), "+f"(c[1]), "+f"(c[2]), "+f"(c[3])
                 : "r"(a[0]), "r"(a[1]), "r"(a[2]), "r"(a[3]), "r"(b[0]), "r"(b[1]));
}
__device__ __forceinline__ void cp_async16(uint32_t dst, const void* src) {
    asm volatile("cp.async.cg.shared.global [%0], [%1], 16;" :: "r"(dst), "l"(src));
}
__device__ __forceinline__ void cp_commit() {
    asm volatile("cp.async.commit_group;" ::: "memory");
}
__device__ __forceinline__ void cp_wait0() {
    asm volatile("cp.async.wait_group 0;" ::: "memory");
}

// ---------------- edge helpers ----------------
__device__ __forceinline__ long long edge_dst(const void* ei, int e) {
    return g_is64 ? ((const long long*)ei)[EE + e] : (long long)((const int*)ei)[EE + e];
}
__device__ __forceinline__ void edge_sd(const void* ei, int e, long long& s, long long& d) {
    if (g_is64) { const long long* p = (const long long*)ei; s = p[e]; d = p[EE + e]; }
    else        { const int*       p = (const int*)ei;       s = p[e]; d = p[EE + e]; }
}

// ---------------- side-stream chain: detect + zero + CSR build ----------------
__global__ void k_zero(const unsigned* __restrict__ ei) {
    int i = blockIdx.x * blockDim.x + threadIdx.x;
    if (i == 0) {
        int all0 = 1;
        #pragma unroll 1
        for (int j = 0; j < 256; j++) all0 &= (ei[2 * j + 1] == 0u);
        g_is64 = all0;
    }
    if (i < NN) g_deg[i] = 0;
}
__global__ void k_count(const void* __restrict__ ei) {
    int e = blockIdx.x * blockDim.x + threadIdx.x;
    if (e >= EE) return;
    atomicAdd(&g_deg[(int)edge_dst(ei, e)], 1);
}
__global__ void k_scan() {
    __shared__ int ssum[1024];
    const int CH = (NN + 1023) / 1024;
    int t = threadIdx.x;
    int base = t * CH;
    int s = 0;
    for (int i = 0; i < CH; i++) { int idx = base + i; if (idx < NN) s += g_deg[idx]; }
    ssum[t] = s;
    __syncthreads();
    for (int off = 1; off < 1024; off <<= 1) {
        int v = (t >= off) ? ssum[t - off] : 0;
        __syncthreads();
        ssum[t] += v;
        __syncthreads();
    }
    int excl = (t == 0) ? 0 : ssum[t - 1];
    for (int i = 0; i < CH; i++) {
        int idx = base + i;
        if (idx < NN) { g_off[idx] = excl; g_cur[idx] = excl; excl += g_deg[idx]; }
    }
    if (t == 1023) g_off[NN] = EE;
}
__global__ void k_fill(const void* __restrict__ ei) {
    int e = blockIdx.x * blockDim.x + threadIdx.x;
    if (e >= EE) return;
    long long s, d;
    edge_sd(ei, e, s, d);
    int pos = atomicAdd(&g_cur[(int)d], 1);
    g_csr_src[pos] = (int)s;
}

// ---------------- main-stream prep: coalesced W^T -> fp16 (smem transpose) ----------------
__global__ __launch_bounds__(256) void k_prep_w(const float* __restrict__ W) {
    __shared__ float t[32][33];
    int n0 = blockIdx.x * 32, k0 = blockIdx.y * 32;
    int tx = threadIdx.x & 31, ty = threadIdx.x >> 5;   // ty in 0..7
    #pragma unroll
    for (int r = ty; r < 32; r += 8)
        t[r][tx] = W[(size_t)(k0 + r) * HSZ + n0 + tx];   // coalesced read (n fast)
    __syncthreads();
    #pragma unroll
    for (int r = ty; r < 32; r += 8) {
        float v = t[tx][r];                                // = W[k0+tx][n0+r]
        g_wt[(size_t)(n0 + r) * HSZ + k0 + tx] = __float2half_rn(v);
    }
}

// ---------------- fused GEMM + attention logits (fp16 single-term, pipelined) ----------------
// CTA tile: M=128 x N=256, K in 4 chunks of 64. 512 threads = 16 warps: 4(M) x 4(N).
// Double-buffered SMEM (110.6KB); B via cp.async, A via register prefetch.
// __launch_bounds__(512, 1): full 128-reg budget -> NO accumulator spills
// (round-13's (512,2) capped regs at 64 and spilled the whole acc file).
#define PITCHB 144
#define A_BUF_SZ 18432            // 128 rows * 144
#define B_BUF_SZ 36864            // 256 rows * 144
#define SA(b) ((b) * A_BUF_SZ)
#define SB(b) (36864 + (b) * B_BUF_SZ)
#define SMEMTOT 110592

__global__ __launch_bounds__(512, 1) void k_gemm_mma(const float* __restrict__ x,
                                                     const float* __restrict__ att_src,
                                                     const float* __restrict__ att_dst) {
    extern __shared__ char smem[];
    uint32_t sb = smem_u32(smem);
    int tid = threadIdx.x;
    int wid = tid >> 5, lane = tid & 31;
    int brow = blockIdx.x * 128;
    int mbase = (wid & 3) * 32;
    int nwarp = wid >> 2;
    int nbase = nwarp * 64;

    auto issue_b = [&](int kc, int buf) {
        int k0 = kc * 64;
        #pragma unroll
        for (int v = 0; v < 4; v++) {
            int g = tid + v * 512;           // 2048 uint4 slots
            int n = g >> 3, sl = g & 7;
            cp_async16(sb + SB(buf) + n * PITCHB + sl * 16,
                       &g_wt[(size_t)n * HSZ + k0 + sl * 8]);
        }
        cp_commit();
    };
    // Load A fp32 and convert to packed fp16 immediately (8 live regs).
    auto load_a = [&](int kc, uint2* ah) {
        int k0 = kc * 64;
        #pragma unroll
        for (int v = 0; v < 4; v++) {
            int g = tid + v * 512;           // 2048 float4 slots
            int r = g >> 4, fq = g & 15;
            int gr = brow + r;
            float4 vv = (gr < NN) ? *(const float4*)&x[(size_t)gr * HSZ + k0 + fq * 4]
                                  : make_float4(0.f, 0.f, 0.f, 0.f);
            __half2 p0 = __floats2half2_rn(vv.x, vv.y);
            __half2 p1 = __floats2half2_rn(vv.z, vv.w);
            ah[v] = make_uint2(*(uint32_t*)&p0, *(uint32_t*)&p1);
        }
    };
    auto store_a = [&](const uint2* ah, int buf) {
        #pragma unroll
        for (int v = 0; v < 4; v++) {
            int g = tid + v * 512;
            int r = g >> 4, fq = g & 15;
            *(uint2*)(smem + SA(buf) + r * PITCHB + fq * 8) = ah[v];
        }
    };

    float acc[2][8][4];
    #pragma unroll
    for (int mt = 0; mt < 2; mt++)
        #pragma unroll
        for (int nt = 0; nt < 8; nt++)
            #pragma unroll
            for (int j = 0; j < 4; j++) acc[mt][nt][j] = 0.f;

    // prologue: stage chunk 0
    issue_b(0, 0);
    {
        uint2 ah[4];
        load_a(0, ah);
        store_a(ah, 0);
    }

    #pragma unroll 1
    for (int kc = 0; kc < 4; kc++) {
        int buf = kc & 1;
        cp_wait0();
        __syncthreads();   // B(kc)+A(kc) visible; all readers of buf^1 done

        uint2 ahr[4];
        if (kc < 3) {
            issue_b(kc + 1, buf ^ 1);
            load_a(kc + 1, ahr);   // LDG latency hides under compute below
        }

        #pragma unroll
        for (int ks = 0; ks < 4; ks++) {
            uint32_t ah[2][4];
            #pragma unroll
            for (int mt = 0; mt < 2; mt++) {
                uint32_t r = mbase + mt * 16 + (lane & 15);
                uint32_t c = ks * 16 + ((lane >> 4) << 3);
                ldsm_x4(ah[mt], sb + SA(buf) + r * PITCHB + c * 2);
            }
            #pragma unroll
            for (int ntg = 0; ntg < 4; ntg++) {
                uint32_t rn = nbase + ntg * 16 + (lane & 7) + (((lane >> 4) & 1) << 3);
                uint32_t ck = ks * 16 + (((lane >> 3) & 1) << 3);
                uint32_t bh[4];
                ldsm_x4(bh, sb + SB(buf) + rn * PITCHB + ck * 2);
                #pragma unroll
                for (int mt = 0; mt < 2; mt++) {
                    #pragma unroll
                    for (int half = 0; half < 2; half++)
                        mma_f16(acc[mt][ntg * 2 + half], ah[mt], &bh[half * 2]);
                }
            }
        }

        if (kc < 3) store_a(ahr, buf ^ 1);   // writes buf^1; readers use buf
    }

    // ---- epilogue 1: write xw as fp16 ----
    #pragma unroll
    for (int mt = 0; mt < 2; mt++) {
        int r0 = brow + mbase + mt * 16 + (lane >> 2);
        #pragma unroll
        for (int nt = 0; nt < 8; nt++) {
            int cc = nbase + nt * 8 + (lane & 3) * 2;
            if (r0 < NN) {
                __half2 p = __floats2half2_rn(acc[mt][nt][0], acc[mt][nt][1]);
                *(uint32_t*)&g_xwh[(size_t)r0 * HSZ + cc] = *(uint32_t*)&p;
            }
            if (r0 + 8 < NN) {
                __half2 p = __floats2half2_rn(acc[mt][nt][2], acc[mt][nt][3]);
                *(uint32_t*)&g_xwh[(size_t)(r0 + 8) * HSZ + cc] = *(uint32_t*)&p;
            }
        }
    }

    // ---- epilogue 2: attention logits from fragments ----
    __syncthreads();                     // all ldsm done before SMEM reuse
    float* att_s = (float*)smem;
    float* att_d = (float*)smem + 256;
    if (tid < 256) { att_s[tid] = att_src[tid]; att_d[tid] = att_dst[tid]; }
    __syncthreads();

    float ds[2][2][2] = {}, dd2[2][2][2] = {};
    #pragma unroll
    for (int mt = 0; mt < 2; mt++)
        #pragma unroll
        for (int nt = 0; nt < 8; nt++) {
            int hh = nt >> 2;
            int colb = nbase + nt * 8 + (lane & 3) * 2;
            #pragma unroll
            for (int j = 0; j < 4; j++) {
                int col = colb + (j & 1);
                float v = acc[mt][nt][j];
                ds[mt][j >> 1][hh]  += v * att_s[col];
                dd2[mt][j >> 1][hh] += v * att_d[col];
            }
        }
    #pragma unroll
    for (int off = 1; off <= 2; off <<= 1) {
        #pragma unroll
        for (int mt = 0; mt < 2; mt++)
            #pragma unroll
            for (int rs = 0; rs < 2; rs++)
                #pragma unroll
                for (int hh = 0; hh < 2; hh++) {
                    ds[mt][rs][hh]  += __shfl_xor_sync(0xFFFFFFFFu, ds[mt][rs][hh], off);
                    dd2[mt][rs][hh] += __shfl_xor_sync(0xFFFFFFFFu, dd2[mt][rs][hh], off);
                }
    }
    if ((lane & 3) == 0) {
        int hb = nwarp * 2;
        #pragma unroll
        for (int mt = 0; mt < 2; mt++)
            #pragma unroll
            for (int rs = 0; rs < 2; rs++) {
                int row = brow + mbase + mt * 16 + (lane >> 2) + rs * 8;
                if (row < NN) {
                    #pragma unroll
                    for (int hh = 0; hh < 2; hh++) {
                        g_asrc[(size_t)row * HH + hb + hh] = ds[mt][rs][hh];
                        g_adst[(size_t)row * HH + hb + hh] = dd2[mt][rs][hh];
                    }
                }
            }
    }
}

// ---------------- single-pass per-dst softmax + aggregation (fp16 gather) ----------------
// Warp per node; 4-edge unroll (round-9/11 operating point: 32 warps/SM).
__device__ __forceinline__ void acc_row(float* acc, const uint4 q, float p) {
    float2 f0 = __half22float2(*(const __half2*)&q.x);
    float2 f1 = __half22float2(*(const __half2*)&q.y);
    float2 f2 = __half22float2(*(const __half2*)&q.z);
    float2 f3 = __half22float2(*(const __half2*)&q.w);
    acc[0] += p * f0.x; acc[1] += p * f0.y;
    acc[2] += p * f1.x; acc[3] += p * f1.y;
    acc[4] += p * f2.x; acc[5] += p * f2.y;
    acc[6] += p * f3.x; acc[7] += p * f3.y;
}

__global__ __launch_bounds__(256) void k_aggregate(float* __restrict__ out,
                                                   const float* __restrict__ bias) {
    int n = blockIdx.x * (blockDim.x >> 5) + (threadIdx.x >> 5);
    if (n >= NN) return;
    int lane = threadIdx.x & 31;
    int h = lane >> 2;

    int beg = g_off[n], end = g_off[n + 1];
    float adn = g_adst[(size_t)n * HH + h];

    float den = 0.f;
    float acc[8] = {};
    int i = beg;
    #pragma unroll 1
    for (; i + 4 <= end; i += 4) {
        int s0 = __ldg(&g_csr_src[i]);
        int s1 = __ldg(&g_csr_src[i + 1]);
        int s2 = __ldg(&g_csr_src[i + 2]);
        int s3 = __ldg(&g_csr_src[i + 3]);
        float e0 = g_asrc[(size_t)s0 * HH + h] + adn;
        float e1 = g_asrc[(size_t)s1 * HH + h] + adn;
        float e2 = g_asrc[(size_t)s2 * HH + h] + adn;
        float e3 = g_asrc[(size_t)s3 * HH + h] + adn;
        uint4 q0 = *(const uint4*)(g_xwh + (size_t)s0 * HSZ + lane * 8);
        uint4 q1 = *(const uint4*)(g_xwh + (size_t)s1 * HSZ + lane * 8);
        uint4 q2 = *(const uint4*)(g_xwh + (size_t)s2 * HSZ + lane * 8);
        uint4 q3 = *(const uint4*)(g_xwh + (size_t)s3 * HSZ + lane * 8);
        e0 = (e0 > 0.f) ? e0 : NEG_SLOPE * e0;
        e1 = (e1 > 0.f) ? e1 : NEG_SLOPE * e1;
        e2 = (e2 > 0.f) ? e2 : NEG_SLOPE * e2;
        e3 = (e3 > 0.f) ? e3 : NEG_SLOPE * e3;
        float p0 = __expf(e0), p1 = __expf(e1), p2 = __expf(e2), p3 = __expf(e3);
        den += (p0 + p1) + (p2 + p3);
        acc_row(acc, q0, p0);
        acc_row(acc, q1, p1);
        acc_row(acc, q2, p2);
        acc_row(acc, q3, p3);
    }
    #pragma unroll 1
    for (; i < end; i++) {
        int s0 = __ldg(&g_csr_src[i]);
        float e0 = g_asrc[(size_t)s0 * HH + h] + adn;
        e0 = (e0 > 0.f) ? e0 : NEG_SLOPE * e0;
        uint4 q0 = *(const uint4*)(g_xwh + (size_t)s0 * HSZ + lane * 8);
        float p0 = __expf(e0);
        den += p0;
        acc_row(acc, q0, p0);
    }

    float inv = 1.f / (den + EPSV);
    const float4* bp = (const float4*)(bias + lane * 8);
    float4 b0 = __ldg(bp), b1 = __ldg(bp + 1);
    float* op = out + (size_t)n * HSZ + lane * 8;
    float4 o0, o1;
    o0.x = fmaxf(acc[0] * inv + b0.x, 0.f);
    o0.y = fmaxf(acc[1] * inv + b0.y, 0.f);
    o0.z = fmaxf(acc[2] * inv + b0.z, 0.f);
    o0.w = fmaxf(acc[3] * inv + b0.w, 0.f);
    o1.x = fmaxf(acc[4] * inv + b1.x, 0.f);
    o1.y = fmaxf(acc[5] * inv + b1.y, 0.f);
    o1.z = fmaxf(acc[6] * inv + b1.z, 0.f);
    o1.w = fmaxf(acc[7] * inv + b1.w, 0.f);
    *(float4*)op = o0;
    *(float4*)(op + 4) = o1;
}

// ---------------- launch ----------------
extern "C" void kernel_launch(void* const* d_in, const int* in_sizes, int n_in,
                              void* d_out, int out_size) {
    const float* x    = (const float*)d_in[0];
    const void*  ei   = d_in[1];
    const float* W    = (const float*)d_in[2];
    const float* asrc = (const float*)d_in[3];
    const float* adst = (const float*)d_in[4];
    const float* bias = (const float*)d_in[5];
    float* out = (float*)d_out;

    cudaFuncSetAttribute(k_gemm_mma, cudaFuncAttributeMaxDynamicSharedMemorySize, SMEMTOT);

    // Fork CSR build onto a side stream so it overlaps the GEMM.
    cudaStream_t s1;
    cudaStreamCreateWithFlags(&s1, cudaStreamNonBlocking);
    cudaEvent_t e0, e1;
    cudaEventCreateWithFlags(&e0, cudaEventDisableTiming);
    cudaEventCreateWithFlags(&e1, cudaEventDisableTiming);

    cudaEventRecord(e0, 0);
    cudaStreamWaitEvent(s1, e0, 0);
    k_zero<<<(NN + 255) / 256, 256, 0, s1>>>((const unsigned*)ei);
    k_count<<<(EE + 255) / 256, 256, 0, s1>>>(ei);
    k_scan<<<1, 1024, 0, s1>>>();
    k_fill<<<(EE + 255) / 256, 256, 0, s1>>>(ei);
    cudaEventRecord(e1, s1);

    k_prep_w<<<dim3(8, 8), 256>>>(W);
    k_gemm_mma<<<(NN + 127) / 128, 512, SMEMTOT>>>(x, asrc, adst);

    cudaStreamWaitEvent(0, e1, 0);
    k_aggregate<<<(NN * 32 + 255) / 256, 256>>>(out, bias);

    cudaEventDestroy(e0);
    cudaEventDestroy(e1);
    cudaStreamDestroy(s1);
}

// round 17
// speedup vs baseline: 1.0054x; 1.0054x over previous
#include <cuda_runtime.h>
#include <cuda_fp16.h>
#include <cstdint>

#define NN 50000
#define EE 800000
#define HH 8
#define CC 32
#define HSZ 256
#define NEG_SLOPE 0.2f
#define EPSV 1e-16f

// ---------------- device scratch (static, no allocation) ----------------
__device__ __align__(16) __half g_xwh[(size_t)NN * HSZ];  // x @ W in fp16  25.6MB
__device__ float g_asrc[NN * HH];
__device__ float g_adst[NN * HH];
__device__ __align__(16) __half g_wt[HSZ * HSZ];          // W^T fp16 [n][k]
__device__ int   g_deg[NN];
__device__ int   g_off[NN + 1];
__device__ int   g_cur[NN];
__device__ int   g_csr_src[EE];
__device__ int   g_is64;

// ---------------- ptx helpers ----------------
__device__ __forceinline__ uint32_t smem_u32(const void* p) {
    uint32_t a;
    asm("{ .reg .u64 t; cvta.to.shared.u64 t, %1; cvt.u32.u64 %0, t; }" : "=r"(a) : "l"(p));
    return a;
}
__device__ __forceinline__ void ldsm_x4(uint32_t* r, uint32_t addr) {
    asm volatile("ldmatrix.sync.aligned.m8n8.x4.shared.b16 {%0,%1,%2,%3}, [%4];"
                 : "=r"(r[0]), "=r"(r[1]), "=r"(r[2]), "=r"(r[3]) : "r"(addr));
}
__device__ __forceinline__ void mma_f16(float* c, const uint32_t* a, const uint32_t* b) {
    asm volatile("mma.sync.aligned.m16n8k16.row.col.f32.f16.f16.f32 "
                 "{%0,%1,%2,%3}, {%4,%5,%6,%7}, {%8,%9}, {%0,%1,%2,%3};"
                 : "+f"(c[0]), "+f"(c[1]), "+f"(c[2]), "+f"(c[3])
                 : "r"(a[0]), "r"(a[1]), "r"(a[2]), "r"(a[3]), "r"(b[0]), "r"(b[1]));
}
__device__ __forceinline__ void cp_async16(uint32_t dst, const void* src) {
    asm volatile("cp.async.cg.shared.global [%0], [%1], 16;" :: "r"(dst), "l"(src));
}
__device__ __forceinline__ void cp_commit() {
    asm volatile("cp.async.commit_group;" ::: "memory");
}
__device__ __forceinline__ void cp_wait0() {
    asm volatile("cp.async.wait_group 0;" ::: "memory");
}

// ---------------- edge helpers ----------------
__device__ __forceinline__ long long edge_dst(const void* ei, int e) {
    return g_is64 ? ((const long long*)ei)[EE + e] : (long long)((const int*)ei)[EE + e];
}
__device__ __forceinline__ void edge_sd(const void* ei, int e, long long& s, long long& d) {
    if (g_is64) { const long long* p = (const long long*)ei; s = p[e]; d = p[EE + e]; }
    else        { const int*       p = (const int*)ei;       s = p[e]; d = p[EE + e]; }
}

// ---------------- side-stream chain: detect + zero + CSR build ----------------
__global__ void k_zero(const unsigned* __restrict__ ei) {
    int i = blockIdx.x * blockDim.x + threadIdx.x;
    if (i == 0) {
        int all0 = 1;
        #pragma unroll 1
        for (int j = 0; j < 256; j++) all0 &= (ei[2 * j + 1] == 0u);
        g_is64 = all0;
    }
    if (i < NN) g_deg[i] = 0;
}
__global__ void k_count(const void* __restrict__ ei) {
    int e = blockIdx.x * blockDim.x + threadIdx.x;
    if (e >= EE) return;
    atomicAdd(&g_deg[(int)edge_dst(ei, e)], 1);
}
__global__ void k_scan() {
    __shared__ int ssum[1024];
    const int CH = (NN + 1023) / 1024;
    int t = threadIdx.x;
    int base = t * CH;
    int s = 0;
    for (int i = 0; i < CH; i++) { int idx = base + i; if (idx < NN) s += g_deg[idx]; }
    ssum[t] = s;
    __syncthreads();
    for (int off = 1; off < 1024; off <<= 1) {
        int v = (t >= off) ? ssum[t - off] : 0;
        __syncthreads();
        ssum[t] += v;
        __syncthreads();
    }
    int excl = (t == 0) ? 0 : ssum[t - 1];
    for (int i = 0; i < CH; i++) {
        int idx = base + i;
        if (idx < NN) { g_off[idx] = excl; g_cur[idx] = excl; excl += g_deg[idx]; }
    }
    if (t == 1023) g_off[NN] = EE;
}
__global__ void k_fill(const void* __restrict__ ei) {
    int e = blockIdx.x * blockDim.x + threadIdx.x;
    if (e >= EE) return;
    long long s, d;
    edge_sd(ei, e, s, d);
    int pos = atomicAdd(&g_cur[(int)d], 1);
    g_csr_src[pos] = (int)s;
}

// ---------------- main-stream prep: coalesced W^T -> fp16 (smem transpose) ----------------
__global__ __launch_bounds__(256) void k_prep_w(const float* __restrict__ W) {
    __shared__ float t[32][33];
    int n0 = blockIdx.x * 32, k0 = blockIdx.y * 32;
    int tx = threadIdx.x & 31, ty = threadIdx.x >> 5;   // ty in 0..7
    #pragma unroll
    for (int r = ty; r < 32; r += 8)
        t[r][tx] = W[(size_t)(k0 + r) * HSZ + n0 + tx];   // coalesced read (n fast)
    __syncthreads();
    #pragma unroll
    for (int r = ty; r < 32; r += 8) {
        float v = t[tx][r];                                // = W[k0+tx][n0+r]
        g_wt[(size_t)(n0 + r) * HSZ + k0 + tx] = __float2half_rn(v);
    }
}

// ---------------- fused GEMM + attention logits (fp16 single-term, pipelined) ----------------
// CTA tile: M=128 x N=256, K in 4 chunks of 64. 512 threads = 16 warps: 4(M) x 4(N).
// Double-buffered SMEM (110.6KB); B via cp.async, A via register prefetch.
// __launch_bounds__(512, 1): full 128-reg budget -> NO accumulator spills
// (round-13's (512,2) capped regs at 64 and spilled the whole acc file).
#define PITCHB 144
#define A_BUF_SZ 18432            // 128 rows * 144
#define B_BUF_SZ 36864            // 256 rows * 144
#define SA(b) ((b) * A_BUF_SZ)
#define SB(b) (36864 + (b) * B_BUF_SZ)
#define SMEMTOT 110592

__global__ __launch_bounds__(512, 1) void k_gemm_mma(const float* __restrict__ x,
                                                     const float* __restrict__ att_src,
                                                     const float* __restrict__ att_dst) {
    extern __shared__ char smem[];
    uint32_t sb = smem_u32(smem);
    int tid = threadIdx.x;
    int wid = tid >> 5, lane = tid & 31;
    int brow = blockIdx.x * 128;
    int mbase = (wid & 3) * 32;
    int nwarp = wid >> 2;
    int nbase = nwarp * 64;

    auto issue_b = [&](int kc, int buf) {
        int k0 = kc * 64;
        #pragma unroll
        for (int v = 0; v < 4; v++) {
            int g = tid + v * 512;           // 2048 uint4 slots
            int n = g >> 3, sl = g & 7;
            cp_async16(sb + SB(buf) + n * PITCHB + sl * 16,
                       &g_wt[(size_t)n * HSZ + k0 + sl * 8]);
        }
        cp_commit();
    };
    // Load A fp32 and convert to packed fp16 immediately (8 live regs).
    auto load_a = [&](int kc, uint2* ah) {
        int k0 = kc * 64;
        #pragma unroll
        for (int v = 0; v < 4; v++) {
            int g = tid + v * 512;           // 2048 float4 slots
            int r = g >> 4, fq = g & 15;
            int gr = brow + r;
            float4 vv = (gr < NN) ? *(const float4*)&x[(size_t)gr * HSZ + k0 + fq * 4]
                                  : make_float4(0.f, 0.f, 0.f, 0.f);
            __half2 p0 = __floats2half2_rn(vv.x, vv.y);
            __half2 p1 = __floats2half2_rn(vv.z, vv.w);
            ah[v] = make_uint2(*(uint32_t*)&p0, *(uint32_t*)&p1);
        }
    };
    auto store_a = [&](const uint2* ah, int buf) {
        #pragma unroll
        for (int v = 0; v < 4; v++) {
            int g = tid + v * 512;
            int r = g >> 4, fq = g & 15;
            *(uint2*)(smem + SA(buf) + r * PITCHB + fq * 8) = ah[v];
        }
    };

    float acc[2][8][4];
    #pragma unroll
    for (int mt = 0; mt < 2; mt++)
        #pragma unroll
        for (int nt = 0; nt < 8; nt++)
            #pragma unroll
            for (int j = 0; j < 4; j++) acc[mt][nt][j] = 0.f;

    // prologue: stage chunk 0
    issue_b(0, 0);
    {
        uint2 ah[4];
        load_a(0, ah);
        store_a(ah, 0);
    }

    #pragma unroll 1
    for (int kc = 0; kc < 4; kc++) {
        int buf = kc & 1;
        cp_wait0();
        __syncthreads();   // B(kc)+A(kc) visible; all readers of buf^1 done

        uint2 ahr[4];
        if (kc < 3) {
            issue_b(kc + 1, buf ^ 1);
            load_a(kc + 1, ahr);   // LDG latency hides under compute below
        }

        #pragma unroll
        for (int ks = 0; ks < 4; ks++) {
            uint32_t ah[2][4];
            #pragma unroll
            for (int mt = 0; mt < 2; mt++) {
                uint32_t r = mbase + mt * 16 + (lane & 15);
                uint32_t c = ks * 16 + ((lane >> 4) << 3);
                ldsm_x4(ah[mt], sb + SA(buf) + r * PITCHB + c * 2);
            }
            #pragma unroll
            for (int ntg = 0; ntg < 4; ntg++) {
                uint32_t rn = nbase + ntg * 16 + (lane & 7) + (((lane >> 4) & 1) << 3);
                uint32_t ck = ks * 16 + (((lane >> 3) & 1) << 3);
                uint32_t bh[4];
                ldsm_x4(bh, sb + SB(buf) + rn * PITCHB + ck * 2);
                #pragma unroll
                for (int mt = 0; mt < 2; mt++) {
                    #pragma unroll
                    for (int half = 0; half < 2; half++)
                        mma_f16(acc[mt][ntg * 2 + half], ah[mt], &bh[half * 2]);
                }
            }
        }

        if (kc < 3) store_a(ahr, buf ^ 1);   // writes buf^1; readers use buf
    }

    // ---- epilogue 1: write xw as fp16 ----
    #pragma unroll
    for (int mt = 0; mt < 2; mt++) {
        int r0 = brow + mbase + mt * 16 + (lane >> 2);
        #pragma unroll
        for (int nt = 0; nt < 8; nt++) {
            int cc = nbase + nt * 8 + (lane & 3) * 2;
            if (r0 < NN) {
                __half2 p = __floats2half2_rn(acc[mt][nt][0], acc[mt][nt][1]);
                *(uint32_t*)&g_xwh[(size_t)r0 * HSZ + cc] = *(uint32_t*)&p;
            }
            if (r0 + 8 < NN) {
                __half2 p = __floats2half2_rn(acc[mt][nt][2], acc[mt][nt][3]);
                *(uint32_t*)&g_xwh[(size_t)(r0 + 8) * HSZ + cc] = *(uint32_t*)&p;
            }
        }
    }

    // ---- epilogue 2: attention logits from fragments ----
    __syncthreads();                     // all ldsm done before SMEM reuse
    float* att_s = (float*)smem;
    float* att_d = (float*)smem + 256;
    if (tid < 256) { att_s[tid] = att_src[tid]; att_d[tid] = att_dst[tid]; }
    __syncthreads();

    float ds[2][2][2] = {}, dd2[2][2][2] = {};
    #pragma unroll
    for (int mt = 0; mt < 2; mt++)
        #pragma unroll
        for (int nt = 0; nt < 8; nt++) {
            int hh = nt >> 2;
            int colb = nbase + nt * 8 + (lane & 3) * 2;
            #pragma unroll
            for (int j = 0; j < 4; j++) {
                int col = colb + (j & 1);
                float v = acc[mt][nt][j];
                ds[mt][j >> 1][hh]  += v * att_s[col];
                dd2[mt][j >> 1][hh] += v * att_d[col];
            }
        }
    #pragma unroll
    for (int off = 1; off <= 2; off <<= 1) {
        #pragma unroll
        for (int mt = 0; mt < 2; mt++)
            #pragma unroll
            for (int rs = 0; rs < 2; rs++)
                #pragma unroll
                for (int hh = 0; hh < 2; hh++) {
                    ds[mt][rs][hh]  += __shfl_xor_sync(0xFFFFFFFFu, ds[mt][rs][hh], off);
                    dd2[mt][rs][hh] += __shfl_xor_sync(0xFFFFFFFFu, dd2[mt][rs][hh], off);
                }
    }
    if ((lane & 3) == 0) {
        int hb = nwarp * 2;
        #pragma unroll
        for (int mt = 0; mt < 2; mt++)
            #pragma unroll
            for (int rs = 0; rs < 2; rs++) {
                int row = brow + mbase + mt * 16 + (lane >> 2) + rs * 8;
                if (row < NN) {
                    #pragma unroll
                    for (int hh = 0; hh < 2; hh++) {
                        g_asrc[(size_t)row * HH + hb + hh] = ds[mt][rs][hh];
                        g_adst[(size_t)row * HH + hb + hh] = dd2[mt][rs][hh];
                    }
                }
            }
    }
}

// ---------------- single-pass per-dst softmax + aggregation (fp16 gather) ----------------
// Warp per node; 4-edge unroll (round-9/11 operating point: 32 warps/SM).
__device__ __forceinline__ void acc_row(float* acc, const uint4 q, float p) {
    float2 f0 = __half22float2(*(const __half2*)&q.x);
    float2 f1 = __half22float2(*(const __half2*)&q.y);
    float2 f2 = __half22float2(*(const __half2*)&q.z);
    float2 f3 = __half22float2(*(const __half2*)&q.w);
    acc[0] += p * f0.x; acc[1] += p * f0.y;
    acc[2] += p * f1.x; acc[3] += p * f1.y;
    acc[4] += p * f2.x; acc[5] += p * f2.y;
    acc[6] += p * f3.x; acc[7] += p * f3.y;
}

__global__ __launch_bounds__(256) void k_aggregate(float* __restrict__ out,
                                                   const float* __restrict__ bias) {
    int n = blockIdx.x * (blockDim.x >> 5) + (threadIdx.x >> 5);
    if (n >= NN) return;
    int lane = threadIdx.x & 31;
    int h = lane >> 2;

    int beg = g_off[n], end = g_off[n + 1];
    float adn = g_adst[(size_t)n * HH + h];

    float den = 0.f;
    float acc[8] = {};
    int i = beg;
    #pragma unroll 1
    for (; i + 4 <= end; i += 4) {
        int s0 = __ldg(&g_csr_src[i]);
        int s1 = __ldg(&g_csr_src[i + 1]);
        int s2 = __ldg(&g_csr_src[i + 2]);
        int s3 = __ldg(&g_csr_src[i + 3]);
        float e0 = g_asrc[(size_t)s0 * HH + h] + adn;
        float e1 = g_asrc[(size_t)s1 * HH + h] + adn;
        float e2 = g_asrc[(size_t)s2 * HH + h] + adn;
        float e3 = g_asrc[(size_t)s3 * HH + h] + adn;
        uint4 q0 = *(const uint4*)(g_xwh + (size_t)s0 * HSZ + lane * 8);
        uint4 q1 = *(const uint4*)(g_xwh + (size_t)s1 * HSZ + lane * 8);
        uint4 q2 = *(const uint4*)(g_xwh + (size_t)s2 * HSZ + lane * 8);
        uint4 q3 = *(const uint4*)(g_xwh + (size_t)s3 * HSZ + lane * 8);
        e0 = (e0 > 0.f) ? e0 : NEG_SLOPE * e0;
        e1 = (e1 > 0.f) ? e1 : NEG_SLOPE * e1;
        e2 = (e2 > 0.f) ? e2 : NEG_SLOPE * e2;
        e3 = (e3 > 0.f) ? e3 : NEG_SLOPE * e3;
        float p0 = __expf(e0), p1 = __expf(e1), p2 = __expf(e2), p3 = __expf(e3);
        den += (p0 + p1) + (p2 + p3);
        acc_row(acc, q0, p0);
        acc_row(acc, q1, p1);
        acc_row(acc, q2, p2);
        acc_row(acc, q3, p3);
    }
    #pragma unroll 1
    for (; i < end; i++) {
        int s0 = __ldg(&g_csr_src[i]);
        float e0 = g_asrc[(size_t)s0 * HH + h] + adn;
        e0 = (e0 > 0.f) ? e0 : NEG_SLOPE * e0;
        uint4 q0 = *(const uint4*)(g_xwh + (size_t)s0 * HSZ + lane * 8);
        float p0 = __expf(e0);
        den += p0;
        acc_row(acc, q0, p0);
    }

    float inv = 1.f / (den + EPSV);
    const float4* bp = (const float4*)(bias + lane * 8);
    float4 b0 = __ldg(bp), b1 = __ldg(bp + 1);
    float* op = out + (size_t)n * HSZ + lane * 8;
    float4 o0, o1;
    o0.x = fmaxf(acc[0] * inv + b0.x, 0.f);
    o0.y = fmaxf(acc[1] * inv + b0.y, 0.f);
    o0.z = fmaxf(acc[2] * inv + b0.z, 0.f);
    o0.w = fmaxf(acc[3] * inv + b0.w, 0.f);
    o1.x = fmaxf(acc[4] * inv + b1.x, 0.f);
    o1.y = fmaxf(acc[5] * inv + b1.y, 0.f);
    o1.z = fmaxf(acc[6] * inv + b1.z, 0.f);
    o1.w = fmaxf(acc[7] * inv + b1.w, 0.f);
    *(float4*)op = o0;
    *(float4*)(op + 4) = o1;
}

// ---------------- launch ----------------
extern "C" void kernel_launch(void* const* d_in, const int* in_sizes, int n_in,
                              void* d_out, int out_size) {
    const float* x    = (const float*)d_in[0];
    const void*  ei   = d_in[1];
    const float* W    = (const float*)d_in[2];
    const float* asrc = (const float*)d_in[3];
    const float* adst = (const float*)d_in[4];
    const float* bias = (const float*)d_in[5];
    float* out = (float*)d_out;

    cudaFuncSetAttribute(k_gemm_mma, cudaFuncAttributeMaxDynamicSharedMemorySize, SMEMTOT);

    // Fork CSR build onto a side stream so it overlaps the GEMM.
    cudaStream_t s1;
    cudaStreamCreateWithFlags(&s1, cudaStreamNonBlocking);
    cudaEvent_t e0, e1;
    cudaEventCreateWithFlags(&e0, cudaEventDisableTiming);
    cudaEventCreateWithFlags(&e1, cudaEventDisableTiming);

    cudaEventRecord(e0, 0);
    cudaStreamWaitEvent(s1, e0, 0);
    k_zero<<<(NN + 255) / 256, 256, 0, s1>>>((const unsigned*)ei);
    k_count<<<(EE + 255) / 256, 256, 0, s1>>>(ei);
    k_scan<<<1, 1024, 0, s1>>>();
    k_fill<<<(EE + 255) / 256, 256, 0, s1>>>(ei);
    cudaEventRecord(e1, s1);

    k_prep_w<<<dim3(8, 8), 256>>>(W);
    k_gemm_mma<<<(NN + 127) / 128, 512, SMEMTOT>>>(x, asrc, adst);

    cudaStreamWaitEvent(0, e1, 0);
    k_aggregate<<<(NN * 32 + 255) / 256, 256>>>(out, bias);

    cudaEventDestroy(e0);
    cudaEventDestroy(e1);
    cudaStreamDestroy(s1);
}